// round 1
// baseline (speedup 1.0000x reference)
#include <cuda_runtime.h>
#include <cstdint>

#define P_CHDROP 0.1f
#define NOISE_STD 0.02f
#define P_TIMEMASK 0.1f
#define T_DIM 2048
#define N_DIM 128
#define MLEN 32

// One thread per float4. N/4 = 32 vec per (b,t) row; T = 2048.
// idx layout: i = ((b*T + t) * 32) + n4
__global__ void __launch_bounds__(256, 8)
eeg_augment_kernel(const float4* __restrict__ x,
                   const float4* __restrict__ chdrop_u,   // [B, 32] float4 view of [B,1,N]
                   const float4* __restrict__ noise,
                   const float* __restrict__ tm_u,        // [B]
                   const int* __restrict__ t0,            // [B]
                   float4* __restrict__ out)
{
    unsigned int i = blockIdx.x * blockDim.x + threadIdx.x;  // < 16,777,216 (fits u32)

    unsigned int n4 = i & 31u;          // float4 index within N
    unsigned int bt = i >> 5;
    unsigned int t  = bt & (T_DIM - 1); // 2048 = 2^11
    unsigned int b  = bt >> 11;

    // Per-sample temporal mask predicate (L1-resident scalars)
    float tu  = __ldg(tm_u + b);
    int   ts  = __ldg(t0 + b);
    bool masked = (tu < P_TIMEMASK) & ((int)t >= ts) & ((int)t < ts + MLEN);

    float4 o;
    if (masked) {
        o.x = 0.0f; o.y = 0.0f; o.z = 0.0f; o.w = 0.0f;
    } else {
        float4 xv = __ldg(x + i);
        float4 nv = __ldg(noise + i);
        float4 cu = __ldg(chdrop_u + (b << 5) + n4);   // [B,1,N] -> b*32 + n4

        o.x = (cu.x < P_CHDROP ? 0.0f : xv.x) + NOISE_STD * nv.x;
        o.y = (cu.y < P_CHDROP ? 0.0f : xv.y) + NOISE_STD * nv.y;
        o.z = (cu.z < P_CHDROP ? 0.0f : xv.z) + NOISE_STD * nv.z;
        o.w = (cu.w < P_CHDROP ? 0.0f : xv.w) + NOISE_STD * nv.w;
    }
    out[i] = o;
}

extern "C" void kernel_launch(void* const* d_in, const int* in_sizes, int n_in,
                              void* d_out, int out_size)
{
    // metadata order: x, chdrop_u, noise, tm_u, t0
    const float4* x      = (const float4*)d_in[0];
    const float4* cu     = (const float4*)d_in[1];
    const float4* noise  = (const float4*)d_in[2];
    const float*  tm_u   = (const float*)d_in[3];
    const int*    t0     = (const int*)d_in[4];
    float4*       out    = (float4*)d_out;

    // total f32 elems = 256*2048*128 = 67,108,864 -> 16,777,216 float4
    const unsigned int nvec = 16777216u;
    const unsigned int threads = 256u;
    const unsigned int blocks = nvec / threads;   // 65536

    eeg_augment_kernel<<<blocks, threads>>>(x, cu, noise, tm_u, t0, out);
}

// round 2
// speedup vs baseline: 1.0036x; 1.0036x over previous
#include <cuda_runtime.h>
#include <cstdint>

#define P_CHDROP 0.1f
#define NOISE_STD 0.02f
#define P_TIMEMASK 0.1f
#define T_DIM 2048
#define MLEN 32

// Each thread handles 2 float4 (coalesced: j and j+256 within a 512-vec block tile).
// Streaming cache hints: x/noise/out have zero reuse -> evict-first keeps L2 from
// thrashing writeback against demand reads.
__global__ void __launch_bounds__(256, 8)
eeg_augment_kernel(const float4* __restrict__ x,
                   const float4* __restrict__ chdrop_u,   // [B, 32] float4 view of [B,1,N]
                   const float4* __restrict__ noise,
                   const float* __restrict__ tm_u,        // [B]
                   const int* __restrict__ t0,            // [B]
                   float4* __restrict__ out)
{
    unsigned int base = blockIdx.x * 512u + threadIdx.x;

    #pragma unroll
    for (int k = 0; k < 2; k++) {
        unsigned int i = base + (unsigned int)k * 256u;

        unsigned int n4 = i & 31u;           // float4 index within N (N/4 = 32)
        unsigned int bt = i >> 5;
        unsigned int t  = bt & (T_DIM - 1);  // T = 2048 = 2^11
        unsigned int b  = bt >> 11;

        float tu = __ldg(tm_u + b);
        int   ts = __ldg(t0 + b);
        bool masked = (tu < P_TIMEMASK) & ((int)t >= ts) & ((int)t < ts + MLEN);

        float4 o;
        if (masked) {
            o.x = 0.0f; o.y = 0.0f; o.z = 0.0f; o.w = 0.0f;
        } else {
            float4 xv = __ldcs(x + i);
            float4 nv = __ldcs(noise + i);
            float4 cu = __ldg(chdrop_u + (b << 5) + n4);   // tiny, reused -> keep cached

            o.x = (cu.x < P_CHDROP ? 0.0f : xv.x) + NOISE_STD * nv.x;
            o.y = (cu.y < P_CHDROP ? 0.0f : xv.y) + NOISE_STD * nv.y;
            o.z = (cu.z < P_CHDROP ? 0.0f : xv.z) + NOISE_STD * nv.z;
            o.w = (cu.w < P_CHDROP ? 0.0f : xv.w) + NOISE_STD * nv.w;
        }
        __stcs(out + i, o);
    }
}

extern "C" void kernel_launch(void* const* d_in, const int* in_sizes, int n_in,
                              void* d_out, int out_size)
{
    // metadata order: x, chdrop_u, noise, tm_u, t0
    const float4* x      = (const float4*)d_in[0];
    const float4* cu     = (const float4*)d_in[1];
    const float4* noise  = (const float4*)d_in[2];
    const float*  tm_u   = (const float*)d_in[3];
    const int*    t0     = (const int*)d_in[4];
    float4*       out    = (float4*)d_out;

    // total f32 elems = 256*2048*128 = 67,108,864 -> 16,777,216 float4
    const unsigned int nvec    = 16777216u;
    const unsigned int threads = 256u;
    const unsigned int blocks  = nvec / 512u;   // 32768, 2 vec4 per thread

    eeg_augment_kernel<<<blocks, threads>>>(x, cu, noise, tm_u, t0, out);
}